// round 4
// baseline (speedup 1.0000x reference)
#include <cuda_runtime.h>
#include <stdint.h>

// Capacity sized for the 4096x4096 problem (16,777,216 elements).
#define MAX_ELEMS   (1u << 24)
#define MAX_BLOCKS  (MAX_ELEMS / 64)
#define MAX_PARTS   (MAX_BLOCKS / 128 + 2)

__device__ float2   g_part[MAX_PARTS];            // per-CTA (min,max) of scales
__device__ float    g_scales[MAX_BLOCKS];         // raw per-block scales (1 MB)
__device__ float    g_dscales[MAX_BLOCKS];        // double-quantized scales (1 MB)
__device__ unsigned char g_codes[MAX_ELEMS / 2];  // 4-bit codes, 2/byte (8 MB)

__device__ __forceinline__ unsigned prmt(unsigned a, unsigned b, unsigned c) {
    unsigned d;
    asm("prmt.b32 %0, %1, %2, %3;" : "=r"(d) : "r"(a), "r"(b), "r"(c));
    return d;
}

// Swizzled per-warp smem address (float index) for element `pos` (0..63) of
// local block `b` (0..31). XOR at float4 granularity -> LDS.128/STS.128
// conflict-free both directions.
__device__ __forceinline__ int sw_addr(int b, int pos) {
    return (b << 6) + (((pos & ~3) ^ ((b & 15) << 2)) | (pos & 3));
}

// Kernel 1: per FP4-block (64 elems) percentile scale + 4-bit code pack.
// CTA = 128 threads = 4 warps. One warp handles 32 blocks (8KB), loaded
// coalesced into a per-warp smem tile; one THREAD then owns one block.
__global__ __launch_bounds__(128) void k_quant(const float* __restrict__ x,
                                               int nblocks, int n) {
    __shared__ float sm[4][2048];   // 4 warps x 8KB

    const int w = threadIdx.x >> 5;
    const int l = threadIdx.x & 31;
    const int warp_blk0 = blockIdx.x * 128 + w * 32;  // first FP4 block of this warp
    const int blk = warp_blk0 + l;                    // this thread's FP4 block
    const bool active = blk < nblocks;
    const long warp_e0 = (long)warp_blk0 * 64;

    float* smw = sm[w];
    bool fast = (warp_blk0 + 32 <= nblocks) && (warp_e0 + 2048 <= (long)n);

    if (fast) {
        // Coalesced: lane l, iter i loads float4 #(i*32+l) of the warp tile.
        const float4* p = reinterpret_cast<const float4*>(x + warp_e0);
        float4* s4 = reinterpret_cast<float4*>(smw);
        #pragma unroll
        for (int i = 0; i < 16; i++) {
            float4 f = p[i * 32 + l];
            int e = i * 128 + 4 * l;        // element offset within warp tile
            s4[sw_addr(e >> 6, e & 63) >> 2] = f;
        }
    } else if (active) {
        // Tail: direct bounded gather into own region (no cross-lane sharing).
        int base = blk * 64;
        for (int i = 0; i < 64; i++) {
            float v = (base + i < n) ? x[base + i] : 0.0f;
            smw[sw_addr(l, i)] = v;
        }
    }
    __syncwarp();

    float scale = 0.0f;
    if (active) {
        const float4* s4 = reinterpret_cast<const float4*>(smw);

        // Pass 1: branchless top-5 of |v|: m1 >= m2 >= m3 >= m4 >= m5
        float m1 = -1.f, m2 = -1.f, m3 = -1.f, m4 = -1.f, m5 = -1.f;
        #pragma unroll
        for (int i = 0; i < 16; i++) {
            float4 f = s4[sw_addr(l, 4 * i) >> 2];
            float q[4] = {f.x, f.y, f.z, f.w};
            #pragma unroll
            for (int u = 0; u < 4; u++) {
                float t = fabsf(q[u]), h;
                h = fmaxf(m1, t); t = fminf(m1, t); m1 = h;
                h = fmaxf(m2, t); t = fminf(m2, t); m2 = h;
                h = fmaxf(m3, t); t = fminf(m3, t); m3 = h;
                h = fmaxf(m4, t); t = fminf(m4, t); m4 = h;
                m5 = fmaxf(m5, t);
            }
        }
        // 95th pct of 64 vals: sorted[59] + 0.85*(sorted[60]-sorted[59])
        scale = fmaxf(m5 + 0.85f * (m4 - m5), 1e-8f);
        g_scales[blk] = scale;

        // Pass 2: quantize via midpoint thresholds (scale > 0).
        // k = #(thresholds below |x|) -> level {0,.75,1,1.5,2,3}; c=(sign<<3)|k
        // FSET mask-counting: 6 FSET + 2 IADD + LOP3 per elem, pack on fma pipe.
        float t1 = 0.375f * scale, t2 = 0.875f * scale, t3 = 1.25f * scale,
              t4 = 1.75f  * scale, t5 = 2.5f  * scale;
        unsigned pk[8];
        #pragma unroll
        for (int j = 0; j < 8; j++) {
            unsigned word = 0;
            #pragma unroll
            for (int half = 0; half < 2; half++) {
                float4 f = s4[sw_addr(l, 8 * j + 4 * half) >> 2];
                float q[4] = {f.x, f.y, f.z, f.w};
                #pragma unroll
                for (int u = 0; u < 4; u++) {
                    float xv = q[u];
                    float a = fabsf(xv);
                    unsigned ma, mb, mc, md, me, ms;
                    asm("set.gt.u32.f32 %0, %1, %2;" : "=r"(ma) : "f"(a), "f"(t1));
                    asm("set.gt.u32.f32 %0, %1, %2;" : "=r"(mb) : "f"(a), "f"(t2));
                    asm("set.gt.u32.f32 %0, %1, %2;" : "=r"(mc) : "f"(a), "f"(t3));
                    asm("set.gt.u32.f32 %0, %1, %2;" : "=r"(md) : "f"(a), "f"(t4));
                    asm("set.gt.u32.f32 %0, %1, %2;" : "=r"(me) : "f"(a), "f"(t5));
                    asm("set.lt.u32.f32 %0, %1, %2;" : "=r"(ms) : "f"(xv), "f"(0.0f));
                    unsigned k = 0u - (ma + mb + mc + md + me);   // count 0..5
                    unsigned c = k | (ms & 8u);
                    word += c * (1u << (4 * (half * 4 + u)));     // IMAD pack
                }
            }
            pk[j] = word;
        }
        uint4* dst = reinterpret_cast<uint4*>(g_codes + (size_t)blk * 32);
        dst[0] = make_uint4(pk[0], pk[1], pk[2], pk[3]);
        dst[1] = make_uint4(pk[4], pk[5], pk[6], pk[7]);
    }

    // CTA reduce of scale min/max -> one float2 partial per CTA (no atomics)
    float smin = active ? scale : __int_as_float(0x7F800000);
    float smax = active ? scale : 0.0f;
    #pragma unroll
    for (int off = 16; off; off >>= 1) {
        smin = fminf(smin, __shfl_xor_sync(0xFFFFFFFFu, smin, off));
        smax = fmaxf(smax, __shfl_xor_sync(0xFFFFFFFFu, smax, off));
    }
    __shared__ float sm_min[4], sm_max[4];
    if (l == 0) { sm_min[w] = smin; sm_max[w] = smax; }
    __syncthreads();
    if (threadIdx.x == 0) {
        float mn = sm_min[0], mx = sm_max[0];
        #pragma unroll
        for (int i = 1; i < 4; i++) { mn = fminf(mn, sm_min[i]); mx = fmaxf(mx, sm_max[i]); }
        g_part[blockIdx.x] = make_float2(mn, mx);
    }
}

// Kernel 2: reduce partials to global (smin,smax) and double-quantize all
// scales (drops scale_min, faithful to source). 1024 threads, 1 block each.
__global__ __launch_bounds__(1024) void k_dscale(int nblocks, int nparts) {
    __shared__ float red_mn[32], red_mx[32];
    __shared__ float s_mn, s_mx;

    float mn = __int_as_float(0x7F800000), mx = 0.0f;
    for (int i = threadIdx.x; i < nparts; i += 1024) {
        float2 p = g_part[i];
        mn = fminf(mn, p.x);
        mx = fmaxf(mx, p.y);
    }
    #pragma unroll
    for (int off = 16; off; off >>= 1) {
        mn = fminf(mn, __shfl_xor_sync(0xFFFFFFFFu, mn, off));
        mx = fmaxf(mx, __shfl_xor_sync(0xFFFFFFFFu, mx, off));
    }
    int wid = threadIdx.x >> 5, lid = threadIdx.x & 31;
    if (lid == 0) { red_mn[wid] = mn; red_mx[wid] = mx; }
    __syncthreads();
    if (wid == 0) {
        mn = red_mn[lid]; mx = red_mx[lid];
        #pragma unroll
        for (int off = 16; off; off >>= 1) {
            mn = fminf(mn, __shfl_xor_sync(0xFFFFFFFFu, mn, off));
            mx = fmaxf(mx, __shfl_xor_sync(0xFFFFFFFFu, mx, off));
        }
        if (lid == 0) { s_mn = mn; s_mx = mx; }
    }
    __syncthreads();
    mn = s_mn; mx = s_mx;

    int b = blockIdx.x * 1024 + threadIdx.x;
    if (b >= nblocks) return;
    float s = g_scales[b];
    float ds;
    if (mx > mn) {
        float ss = __fdiv_rn(mx - mn, 255.0f);
        float q = rintf(__fdiv_rn(s - mn, ss));   // jnp.round == half-even == rintf
        q = fminf(fmaxf(q, 0.0f), 255.0f);
        ds = q * ss;
    } else {
        ds = 0.0f;  // q_scales = 0 when smax == smin
    }
    g_dscales[b] = ds;
}

// Kernel 3: PRMT-based decode of 8 codes/thread, multiply by dequantized
// scale. Levels are exact in the high 16 bits of fp32, so decode = byte
// table lookups. ~4 alu ops/elem -> memory-bound.
__global__ __launch_bounds__(256) void k_dequant(float* __restrict__ out, int n) {
    int t = blockIdx.x * 256 + threadIdx.x;
    int e = t * 8;
    if (e >= n) return;

    float ds = g_dscales[e >> 6];
    unsigned w = *reinterpret_cast<const unsigned*>(g_codes + (e >> 1));

    // High/low byte tables of bf16(level[k]), k=0..5: {0,.75,1,1.5,2,3}
    const unsigned aH = 0x3F3F3F00u, bH = 0x00004040u;   // H[k]
    const unsigned aL = 0xC0804000u, bL = 0x00004000u;   // L[k]

    unsigned ksel = w & 0x77777777u;
    unsigned kshi = ksel >> 16;
    unsigned hi0 = prmt(aH, bH, ksel);   // byte i = H[k_i], elems 0..3
    unsigned hi1 = prmt(aH, bH, kshi);   // elems 4..7
    unsigned lo0 = prmt(aL, bL, ksel);
    unsigned lo1 = prmt(aL, bL, kshi);

    // Sign masks via PRMT sign-replicate mode (selector nibble bit3 set).
    unsigned w4 = w << 4;                  // even elems' sign -> byte MSBs
    unsigned sE = prmt(w4, w4, 0xBA98u);   // byte j = FF if elem 2j negative
    unsigned sO = prmt(w,  w,  0xBA98u);   // byte j = FF if elem 2j+1 negative
    unsigned s0123 = prmt(sE, sO, 0x5140u);
    unsigned s4567 = prmt(sE, sO, 0x7362u);
    hi0 |= s0123 & 0x80808080u;            // one LOP3 each
    hi1 |= s4567 & 0x80808080u;

    // Pack byte pairs into two bf16-in-hi16 values per word.
    unsigned p01 = prmt(hi0, lo0, 0x1504u);  // [H1 L1 H0 L0]
    unsigned p23 = prmt(hi0, lo0, 0x3726u);
    unsigned p45 = prmt(hi1, lo1, 0x1504u);
    unsigned p67 = prmt(hi1, lo1, 0x3726u);

    float r[8];
    r[0] = __uint_as_float(p01 << 16)          * ds;
    r[1] = __uint_as_float(p01 & 0xFFFF0000u)  * ds;
    r[2] = __uint_as_float(p23 << 16)          * ds;
    r[3] = __uint_as_float(p23 & 0xFFFF0000u)  * ds;
    r[4] = __uint_as_float(p45 << 16)          * ds;
    r[5] = __uint_as_float(p45 & 0xFFFF0000u)  * ds;
    r[6] = __uint_as_float(p67 << 16)          * ds;
    r[7] = __uint_as_float(p67 & 0xFFFF0000u)  * ds;

    if (e + 8 <= n) {
        float4* o = reinterpret_cast<float4*>(out + e);
        o[0] = make_float4(r[0], r[1], r[2], r[3]);
        o[1] = make_float4(r[4], r[5], r[6], r[7]);
    } else {
        for (int i = 0; i < 8 && e + i < n; i++) out[e + i] = r[i];
    }
}

extern "C" void kernel_launch(void* const* d_in, const int* in_sizes, int n_in,
                              void* d_out, int out_size) {
    const float* x = (const float*)d_in[0];
    float* out = (float*)d_out;
    int n = in_sizes[0];
    int nblocks = (n + 63) / 64;
    int nparts = (nblocks + 127) / 128;

    k_quant<<<nparts, 128>>>(x, nblocks, n);
    k_dscale<<<(nblocks + 1023) / 1024, 1024>>>(nblocks, nparts);
    int nthreads3 = (n + 7) / 8;
    k_dequant<<<(nthreads3 + 255) / 256, 256>>>(out, n);
}

// round 5
// speedup vs baseline: 1.1886x; 1.1886x over previous
#include <cuda_runtime.h>
#include <stdint.h>

// Capacity sized for the 4096x4096 problem (16,777,216 elements).
#define MAX_ELEMS   (1u << 24)
#define MAX_BLOCKS  (MAX_ELEMS / 64)
#define MAX_PARTS   (MAX_BLOCKS / 64 + 2)

__device__ float2   g_part[MAX_PARTS];            // per-CTA (min,max) of scales
__device__ float    g_scales[MAX_BLOCKS];         // raw per-block scales (1 MB)
__device__ float    g_dscales[MAX_BLOCKS];        // double-quantized scales (1 MB)
__device__ unsigned char g_codes[MAX_ELEMS / 2];  // 4-bit codes, 2/byte (8 MB)

__device__ __forceinline__ unsigned prmt(unsigned a, unsigned b, unsigned c) {
    unsigned d;
    asm("prmt.b32 %0, %1, %2, %3;" : "=r"(d) : "r"(a), "r"(b), "r"(c));
    return d;
}

// Swizzle at float4 granularity: conflict-free for BOTH the coalesced staging
// write (p = i*32 + l) and the per-thread read (p = l*8 + i).
__device__ __forceinline__ int swz(int p) { return p ^ ((p >> 3) & 7); }

// Kernel 1: per FP4-block (64 elems) percentile scale + 4-bit code pack.
// CTA = 128 threads = 4 warps. One warp handles 16 blocks (4KB smem tile);
// a PAIR of lanes owns one block (32 elems each), merged via shfl.
__global__ __launch_bounds__(128, 8) void k_quant(const float* __restrict__ x,
                                                  int nblocks, int n) {
    __shared__ float sm[4][1024];   // 4 warps x 4KB

    const int w = threadIdx.x >> 5;
    const int l = threadIdx.x & 31;
    const int warp_blk0 = blockIdx.x * 64 + w * 16;   // first FP4 block of warp
    const int blk = warp_blk0 + (l >> 1);             // this pair's FP4 block
    const bool active = blk < nblocks;
    const long warp_e0 = (long)warp_blk0 * 64;        // first element of warp

    float4* s4 = reinterpret_cast<float4*>(sm[w]);
    bool fast = (warp_blk0 + 16 <= nblocks) && (warp_e0 + 1024 <= (long)n);

    if (fast) {
        const float4* p = reinterpret_cast<const float4*>(x + warp_e0);
        #pragma unroll
        for (int i = 0; i < 8; i++)
            s4[swz(i * 32 + l)] = p[i * 32 + l];
    } else if (active) {
        // Tail: bounded gather of this lane's 32 elems (half block).
        int base = blk * 64 + (l & 1) * 32;
        for (int j = 0; j < 32; j++) {
            float v = (base + j < n) ? x[base + j] : 0.0f;
            int p4 = l * 8 + (j >> 2);
            sm[w][swz(p4) * 4 + (j & 3)] = v;
        }
    }
    __syncwarp();

    float scale = 0.0f;
    if (active) {
        // Pass 1: branchless top-5 of |v| over this lane's 32 elems.
        float m1 = -1.f, m2 = -1.f, m3 = -1.f, m4 = -1.f, m5 = -1.f;
        #pragma unroll
        for (int i = 0; i < 8; i++) {
            float4 f = s4[swz(l * 8 + i)];
            float q[4] = {f.x, f.y, f.z, f.w};
            #pragma unroll
            for (int u = 0; u < 4; u++) {
                float t = fabsf(q[u]), h;
                h = fmaxf(m1, t); t = fminf(m1, t); m1 = h;
                h = fmaxf(m2, t); t = fminf(m2, t); m2 = h;
                h = fmaxf(m3, t); t = fminf(m3, t); m3 = h;
                h = fmaxf(m4, t); t = fminf(m4, t); m4 = h;
                m5 = fmaxf(m5, t);
            }
        }
        // Merge with partner lane's sorted-5: exact 4th/5th largest of union.
        float a1 = __shfl_xor_sync(0xFFFFFFFFu, m1, 1);
        float a2 = __shfl_xor_sync(0xFFFFFFFFu, m2, 1);
        float a3 = __shfl_xor_sync(0xFFFFFFFFu, m3, 1);
        float a4 = __shfl_xor_sync(0xFFFFFFFFu, m4, 1);
        float a5 = __shfl_xor_sync(0xFFFFFFFFu, m5, 1);
        float o4 = fmaxf(fmaxf(fminf(m1, a3), fminf(m2, a2)),
                         fmaxf(fminf(m3, a1), fmaxf(m4, a4)));
        float o5 = fmaxf(fmaxf(fmaxf(fminf(m1, a4), fminf(m2, a3)),
                               fmaxf(fminf(m3, a2), fminf(m4, a1))),
                         fmaxf(m5, a5));
        // 95th pct of 64 vals: sorted[59] + 0.85*(sorted[60]-sorted[59])
        scale = fmaxf(o5 + 0.85f * (o4 - o5), 1e-8f);
        if ((l & 1) == 0) g_scales[blk] = scale;

        // Pass 2: magic-bits fp4 rounding on y = |x| / scale.
        // clamp y to [0.75, 3.0]; k = (bits(y_c) + half-mant-ulp - 252<<22)>>22
        // gives nearest level index 1..5 with boundaries {.875,1.25,1.75,2.5};
        // k=0 iff y < 0.375 via one set.ge mask.
        float r = __frcp_rn(scale);
        unsigned pk[4];
        #pragma unroll
        for (int j = 0; j < 4; j++) {
            unsigned word = 0;
            #pragma unroll
            for (int half = 0; half < 2; half++) {
                float4 f = s4[swz(l * 8 + 2 * j + half)];
                float q[4] = {f.x, f.y, f.z, f.w};
                #pragma unroll
                for (int u = 0; u < 4; u++) {
                    float xv = q[u];
                    float y = fabsf(xv) * r;
                    float m = fminf(fmaxf(y, 0.75f), 3.0f);
                    unsigned k = (__float_as_uint(m) - 0x3EE00000u) >> 22;
                    unsigned zm;
                    asm("set.ge.u32.f32 %0, %1, %2;" : "=r"(zm) : "f"(y), "f"(0.375f));
                    unsigned xs = __float_as_uint(xv) >> 28;
                    unsigned c = (k & zm) | (xs & 8u);
                    word += c * (1u << (4 * (half * 4 + u)));
                }
            }
            pk[j] = word;
        }
        // 32 codes = 16 bytes; pair writes the block's 32-byte code line.
        uint4* dst = reinterpret_cast<uint4*>(g_codes + (size_t)blk * 32 + (l & 1) * 16);
        *dst = make_uint4(pk[0], pk[1], pk[2], pk[3]);
    }

    // CTA reduce of scale min/max -> one float2 partial per CTA (no atomics)
    float smin = active ? scale : __int_as_float(0x7F800000);
    float smax = active ? scale : 0.0f;
    #pragma unroll
    for (int off = 16; off; off >>= 1) {
        smin = fminf(smin, __shfl_xor_sync(0xFFFFFFFFu, smin, off));
        smax = fmaxf(smax, __shfl_xor_sync(0xFFFFFFFFu, smax, off));
    }
    __shared__ float sm_min[4], sm_max[4];
    if (l == 0) { sm_min[w] = smin; sm_max[w] = smax; }
    __syncthreads();
    if (threadIdx.x == 0) {
        float mn = sm_min[0], mx = sm_max[0];
        #pragma unroll
        for (int i = 1; i < 4; i++) { mn = fminf(mn, sm_min[i]); mx = fmaxf(mx, sm_max[i]); }
        g_part[blockIdx.x] = make_float2(mn, mx);
    }
}

// Kernel 2: reduce partials to global (smin,smax) and double-quantize all
// scales (drops scale_min, faithful to source).
__global__ __launch_bounds__(1024) void k_dscale(int nblocks, int nparts) {
    __shared__ float red_mn[32], red_mx[32];
    __shared__ float s_mn, s_mx;

    float mn = __int_as_float(0x7F800000), mx = 0.0f;
    for (int i = threadIdx.x; i < nparts; i += 1024) {
        float2 p = g_part[i];
        mn = fminf(mn, p.x);
        mx = fmaxf(mx, p.y);
    }
    #pragma unroll
    for (int off = 16; off; off >>= 1) {
        mn = fminf(mn, __shfl_xor_sync(0xFFFFFFFFu, mn, off));
        mx = fmaxf(mx, __shfl_xor_sync(0xFFFFFFFFu, mx, off));
    }
    int wid = threadIdx.x >> 5, lid = threadIdx.x & 31;
    if (lid == 0) { red_mn[wid] = mn; red_mx[wid] = mx; }
    __syncthreads();
    if (wid == 0) {
        mn = red_mn[lid]; mx = red_mx[lid];
        #pragma unroll
        for (int off = 16; off; off >>= 1) {
            mn = fminf(mn, __shfl_xor_sync(0xFFFFFFFFu, mn, off));
            mx = fmaxf(mx, __shfl_xor_sync(0xFFFFFFFFu, mx, off));
        }
        if (lid == 0) { s_mn = mn; s_mx = mx; }
    }
    __syncthreads();
    mn = s_mn; mx = s_mx;

    int b = blockIdx.x * 1024 + threadIdx.x;
    if (b >= nblocks) return;
    float s = g_scales[b];
    float ds;
    if (mx > mn) {
        float ss = __fdiv_rn(mx - mn, 255.0f);
        float q = rintf(__fdiv_rn(s - mn, ss));   // jnp.round == half-even == rintf
        q = fminf(fmaxf(q, 0.0f), 255.0f);
        ds = q * ss;
    } else {
        ds = 0.0f;  // q_scales = 0 when smax == smin
    }
    g_dscales[b] = ds;
}

// Kernel 3: PRMT-based decode of 8 codes/thread, multiply by dequantized
// scale. Levels are exact in the high 16 bits of fp32 (bf16), so decode =
// byte table lookups.
__global__ __launch_bounds__(256) void k_dequant(float* __restrict__ out, int n) {
    int t = blockIdx.x * 256 + threadIdx.x;
    int e = t * 8;
    if (e >= n) return;

    float ds = g_dscales[e >> 6];
    unsigned w = *reinterpret_cast<const unsigned*>(g_codes + (e >> 1));

    // High/low byte tables of bf16(level[k]), k=0..5: {0,.75,1,1.5,2,3}
    const unsigned aH = 0x3F3F3F00u, bH = 0x00004040u;   // H[k]
    const unsigned aL = 0xC0804000u, bL = 0x00004000u;   // L[k]

    unsigned ksel = w & 0x77777777u;
    unsigned kshi = ksel >> 16;
    unsigned hi0 = prmt(aH, bH, ksel);   // byte i = H[k_i], elems 0..3
    unsigned hi1 = prmt(aH, bH, kshi);   // elems 4..7
    unsigned lo0 = prmt(aL, bL, ksel);
    unsigned lo1 = prmt(aL, bL, kshi);

    // Sign masks via PRMT sign-replicate mode (selector nibble bit3 set).
    unsigned w4 = w << 4;                  // even elems' sign -> byte MSBs
    unsigned sE = prmt(w4, w4, 0xBA98u);   // byte j = FF if elem 2j negative
    unsigned sO = prmt(w,  w,  0xBA98u);   // byte j = FF if elem 2j+1 negative
    unsigned s0123 = prmt(sE, sO, 0x5140u);
    unsigned s4567 = prmt(sE, sO, 0x7362u);
    hi0 |= s0123 & 0x80808080u;
    hi1 |= s4567 & 0x80808080u;

    // Pack byte pairs into two bf16-in-hi16 values per word.
    unsigned p01 = prmt(hi0, lo0, 0x1504u);  // [H1 L1 H0 L0]
    unsigned p23 = prmt(hi0, lo0, 0x3726u);
    unsigned p45 = prmt(hi1, lo1, 0x1504u);
    unsigned p67 = prmt(hi1, lo1, 0x3726u);

    float r[8];
    r[0] = __uint_as_float(p01 << 16)          * ds;
    r[1] = __uint_as_float(p01 & 0xFFFF0000u)  * ds;
    r[2] = __uint_as_float(p23 << 16)          * ds;
    r[3] = __uint_as_float(p23 & 0xFFFF0000u)  * ds;
    r[4] = __uint_as_float(p45 << 16)          * ds;
    r[5] = __uint_as_float(p45 & 0xFFFF0000u)  * ds;
    r[6] = __uint_as_float(p67 << 16)          * ds;
    r[7] = __uint_as_float(p67 & 0xFFFF0000u)  * ds;

    if (e + 8 <= n) {
        float4* o = reinterpret_cast<float4*>(out + e);
        o[0] = make_float4(r[0], r[1], r[2], r[3]);
        o[1] = make_float4(r[4], r[5], r[6], r[7]);
    } else {
        for (int i = 0; i < 8 && e + i < n; i++) out[e + i] = r[i];
    }
}

extern "C" void kernel_launch(void* const* d_in, const int* in_sizes, int n_in,
                              void* d_out, int out_size) {
    const float* x = (const float*)d_in[0];
    float* out = (float*)d_out;
    int n = in_sizes[0];
    int nblocks = (n + 63) / 64;
    int nparts = (nblocks + 63) / 64;          // one partial per k_quant CTA

    k_quant<<<nparts, 128>>>(x, nblocks, n);
    k_dscale<<<(nblocks + 1023) / 1024, 1024>>>(nblocks, nparts);
    int nthreads3 = (n + 7) / 8;
    k_dequant<<<(nthreads3 + 255) / 256, 256>>>(out, n);
}